// round 12
// baseline (speedup 1.0000x reference)
#include <cuda_runtime.h>
#include <cstdint>

#define NN 100000
#define NE 3200000
#define H  32

typedef unsigned long long ull;

// __device__ scratch (no allocations allowed)
__device__ float4 g_L1q[H];                       // (A,B,C,0): h1 = relu(A*n + B*t + C)
__device__ __align__(16) float4 g_sums4[NN];      // xyz = sums, w = count

// ---- packed f32x2 helpers (ptxas will not auto-fuse these) ----
__device__ __forceinline__ ull ffma2(ull a, ull b, ull c) {
    ull d;
    asm("fma.rn.f32x2 %0, %1, %2, %3;" : "=l"(d) : "l"(a), "l"(b), "l"(c));
    return d;
}
__device__ __forceinline__ ull fmul2(ull a, ull b) {
    ull d;
    asm("mul.rn.f32x2 %0, %1, %2;" : "=l"(d) : "l"(a), "l"(b));
    return d;
}
__device__ __forceinline__ ull fadd2(ull a, ull b) {
    ull d;
    asm("add.rn.f32x2 %0, %1, %2;" : "=l"(d) : "l"(a), "l"(b));
    return d;
}
__device__ __forceinline__ ull pack2(float lo, float hi) {
    ull r;
    asm("mov.b64 %0, {%1, %2};" : "=l"(r) : "f"(lo), "f"(hi));
    return r;
}
__device__ __forceinline__ float2 unpack2(ull v) {
    float2 f;
    asm("mov.b64 {%0, %1}, %2;" : "=f"(f.x), "=f"(f.y) : "l"(v));
    return f;
}
__device__ __forceinline__ ull relu2(ull v) {
    float2 f = unpack2(v);
    return pack2(fmaxf(f.x, 0.0f), fmaxf(f.y, 0.0f));
}

// ---------------------------------------------------------------------------
__global__ void prep_kernel(const float* __restrict__ W1,
                            const float* __restrict__ gamma,
                            const float* __restrict__ beta,
                            const float* __restrict__ mean,
                            const float* __restrict__ var) {
    int k = threadIdx.x;
    if (k < H) {
        float s = gamma[k] * rsqrtf(var[k] + 1e-5f);
        g_L1q[k] = make_float4(W1[k] * s, W1[H + k] * s, beta[k] - mean[k] * s, 0.0f);
    }
}

__global__ void zero_kernel() {
    int i = blockIdx.x * blockDim.x + threadIdx.x;
    if (i < NN) g_sums4[i] = make_float4(0.0f, 0.0f, 0.0f, 0.0f);
}

// ---------------------------------------------------------------------------
// ONE edge per thread, 85-reg cap -> 24 warps/SM (6/SMSP) for latency hiding.
__global__ void __launch_bounds__(256, 3) edge_kernel(
    const float* __restrict__ x,
    const int* __restrict__ ei,
    const float* __restrict__ W2, const float* __restrict__ b2,
    const float* __restrict__ W3, const float* __restrict__ b3,
    const float* __restrict__ W4,
    const float* __restrict__ W5, const float* __restrict__ b5,
    float* __restrict__ out_m)
{
    __shared__ __align__(16) float sW2[H * H];    // row-major [j][k]
    __shared__ __align__(16) float sW3T[H * H];   // transposed [k][j]
    __shared__ __align__(16) float4 sL1[H];
    __shared__ __align__(16) float sb2[H], sb3[H], sW4[H], sW5[H];
    __shared__ float sb5v;

    int tid = threadIdx.x;
    for (int t = tid; t < H * H; t += 256) {
        sW2[t] = W2[t];
        int k = t >> 5, j = t & 31;
        sW3T[t] = W3[j * H + k];
    }
    if (tid < H) {
        sL1[tid] = g_L1q[tid];
        sb2[tid] = b2[tid];
        sb3[tid] = b3[tid];
        sW4[tid] = W4[tid];
        sW5[tid] = W5[tid];
    }
    if (tid == 0) sb5v = b5[0];
    __syncthreads();

    int e = blockIdx.x * 256 + tid;               // grid covers exactly NE

    int ni = ei[e];
    int nj = ei[NE + e];
    if ((unsigned)ni >= NN || (unsigned)nj >= NN) return;

    float xi0 = __ldg(&x[3 * ni + 0]), xi1 = __ldg(&x[3 * ni + 1]), xi2 = __ldg(&x[3 * ni + 2]);
    float xj0 = __ldg(&x[3 * nj + 0]), xj1 = __ldg(&x[3 * nj + 1]), xj2 = __ldg(&x[3 * nj + 2]);

    float d0 = xi0 - xj0, d1 = xi1 - xj1, d2 = xi2 - xj2;
    float nsq = d0 * d0 + d1 * d1 + d2 * d2;
    float dot = xi0 * xj0 + xi1 * xj1 + xi2 * xj2;

    float nrm = log1pf(nsq);
    float dts = copysignf(log1pf(fabsf(dot)), dot);

    // ---- fused layer1 + layer2: acc = b2 + sum_j relu(l1_j) * W2[j,:] ----
    ull acc[H / 2];
    {
        const ull* b2p = (const ull*)sb2;
#pragma unroll
        for (int q = 0; q < H / 2; q++) acc[q] = b2p[q];
    }
#pragma unroll 4
    for (int j = 0; j < H; j++) {
        float4 c = sL1[j];
        float h = fmaxf(fmaf(nrm, c.x, fmaf(dts, c.y, c.z)), 0.0f);
        ull hp = pack2(h, h);
        const ulonglong2* row = (const ulonglong2*)(sW2 + j * H);
#pragma unroll
        for (int q = 0; q < H / 4; q++) {
            ulonglong2 w = row[q];
            acc[2 * q + 0] = ffma2(hp, w.x, acc[2 * q + 0]);
            acc[2 * q + 1] = ffma2(hp, w.y, acc[2 * q + 1]);
        }
    }

    // ---- h2 = relu(acc) IN PLACE ----
#pragma unroll
    for (int q = 0; q < H / 2; q++) acc[q] = relu2(acc[q]);

    // ---- gate: wgt = sigmoid(h2 . W5 + b5) ----
    float wgt;
    {
        const ull* w5p = (const ull*)sW5;
        ull z0 = 0, z1 = 0;
#pragma unroll
        for (int q = 0; q < H / 2; q += 2) {
            z0 = ffma2(acc[q], w5p[q], z0);
            z1 = ffma2(acc[q + 1], w5p[q + 1], z1);
        }
        float2 f = unpack2(fadd2(z0, z1));
        wgt = 1.0f / (1.0f + expf(-(f.x + f.y + sb5v)));
    }

    // ---- m = h2 * wgt, write out ----
    {
        ull wp = pack2(wgt, wgt);
        ulonglong2* mo = (ulonglong2*)(out_m + (long)e * H);
#pragma unroll
        for (int q = 0; q < H / 4; q++) {
            ulonglong2 v;
            v.x = fmul2(acc[2 * q + 0], wp);
            v.y = fmul2(acc[2 * q + 1], wp);
            mo[q] = v;
        }
    }

    // ---- phi_x, k-outer vs transposed W3 ----
    float phix0 = 0.0f, phix1 = 0.0f;
#pragma unroll 4
    for (int k = 0; k < H; k++) {
        const ulonglong2* row = (const ulonglong2*)(sW3T + k * H);
        ull s0 = 0, s1 = 0;
#pragma unroll
        for (int q = 0; q < H / 4; q++) {
            ulonglong2 w = row[q];
            s0 = ffma2(acc[2 * q + 0], w.x, s0);
            s1 = ffma2(acc[2 * q + 1], w.y, s1);
        }
        float2 f = unpack2(fadd2(s0, s1));
        float a3 = f.x + f.y;
        float u = fmaxf(fmaf(wgt, a3, sb3[k]), 0.0f);
        if (k & 1) phix1 = fmaf(u, sW4[k], phix1);
        else       phix0 = fmaf(u, sW4[k], phix0);
    }
    float phix = phix0 + phix1;

    // ---- scatter-mean: 4 scalar reductions onto the float4 cell ----
    float u0 = fminf(fmaxf(d0 * phix, -100.0f), 100.0f);
    float u1 = fminf(fmaxf(d1 * phix, -100.0f), 100.0f);
    float u2 = fminf(fmaxf(d2 * phix, -100.0f), 100.0f);
    float* cell = (float*)&g_sums4[ni];
    atomicAdd(cell + 0, u0);
    atomicAdd(cell + 1, u1);
    atomicAdd(cell + 2, u2);
    atomicAdd(cell + 3, 1.0f);
}

// ---------------------------------------------------------------------------
__global__ void node_kernel(const float* __restrict__ x, float* __restrict__ out_x) {
    int n = blockIdx.x * blockDim.x + threadIdx.x;
    if (n < NN) {
        float4 s = g_sums4[n];
        float inv = 1.0f / fmaxf(s.w, 1.0f);
        out_x[3 * n + 0] = x[3 * n + 0] + s.x * inv;
        out_x[3 * n + 1] = x[3 * n + 1] + s.y * inv;
        out_x[3 * n + 2] = x[3 * n + 2] + s.z * inv;
    }
}

// ---------------------------------------------------------------------------
extern "C" void kernel_launch(void* const* d_in, const int* in_sizes, int n_in,
                              void* d_out, int out_size) {
    const float* x   = (const float*)d_in[0];
    const int*   ei  = (const int*)d_in[1];     // int32 (jax default x64-disabled)
    const float* W1  = (const float*)d_in[2];
    const float* gma = (const float*)d_in[3];
    const float* bta = (const float*)d_in[4];
    const float* mea = (const float*)d_in[5];
    const float* var = (const float*)d_in[6];
    const float* W2  = (const float*)d_in[7];
    const float* b2  = (const float*)d_in[8];
    const float* W3  = (const float*)d_in[9];
    const float* b3  = (const float*)d_in[10];
    const float* W4  = (const float*)d_in[11];
    const float* W5  = (const float*)d_in[12];
    const float* b5  = (const float*)d_in[13];

    float* out_x = (float*)d_out;          // x_tilde: [NN, 3]
    float* out_m = out_x + (long)NN * 3;   // m: [NE, H]

    zero_kernel<<<(NN + 255) / 256, 256>>>();
    prep_kernel<<<1, 32>>>(W1, gma, bta, mea, var);
    edge_kernel<<<NE / 256, 256>>>(x, ei, W2, b2, W3, b3, W4, W5, b5, out_m);  // 1 edge/thread
    node_kernel<<<(NN + 255) / 256, 256>>>(x, out_x);
}